// round 6
// baseline (speedup 1.0000x reference)
#include <cuda_runtime.h>
#include <cstdint>

// out[0, z, r, c, ch] = in[0, z_idx[z], row_idx[r], col_idx[c], 0]
// in (1,128,128,128,32) f32; idx arrays 64 x int32; out (1,64,64,64,32) f32.
//
// Block = 256 contiguous output voxels = 32 KB output tile.
// Phase 1: one gather per thread -> vals[256] in smem.
// Phase 2: expand vals into a 32 KB smem tile (LDS broadcast -> STS.128,
//          conflict-free: 8 lanes share a word, warp writes contiguous 512B).
// Phase 3: ONE cp.async.bulk (TMA) store of the whole 32 KB tile to GMEM.
//          No STG instructions at all -> store stream runs on the TMA/LTS
//          path, fully decoupled from SM issue and scoreboards.

__device__ __forceinline__ uint32_t smem_u32(const void* p) {
    return (uint32_t)__cvta_generic_to_shared(p);
}

__global__ __launch_bounds__(256) void sd3d_kernel(
    const float* __restrict__ in,
    const int*   __restrict__ z_idx,
    const int*   __restrict__ row_idx,
    const int*   __restrict__ col_idx,
    float4*      __restrict__ out)
{
    __shared__ float vals[256];
    __shared__ alignas(128) float4 tile[2048];   // 32 KB

    int tid = threadIdx.x;
    int v = blockIdx.x * 256 + tid;       // voxel id, 0 .. 64^3-1
    int c = v & 63;
    int r = (v >> 6) & 63;
    int z = v >> 12;

    int zz = __ldg(z_idx + z);            // warp-uniform
    int rr = __ldg(row_idx + r);          // warp-uniform
    int cc = __ldg(col_idx + c);

    vals[tid] = __ldg(in + ((((long)zz * 128 + rr) * 128 + cc) << 5));
    __syncthreads();

    // Expand into the tile: float4 index f = i*256 + tid maps to voxel f>>3.
#pragma unroll
    for (int i = 0; i < 8; i++) {
        float x = vals[(i * 256 + tid) >> 3];
        tile[i * 256 + tid] = make_float4(x, x, x, x);
    }

    // Make generic-proxy smem writes visible to the async (TMA) proxy.
    asm volatile("fence.proxy.async.shared::cta;" ::: "memory");
    __syncthreads();

    if (tid == 0) {
        uint64_t gdst = (uint64_t)(out + (size_t)blockIdx.x * 2048);
        uint32_t ssrc = smem_u32(tile);
        asm volatile(
            "cp.async.bulk.global.shared::cta.bulk_group [%0], [%1], %2;"
            :: "l"(gdst), "r"(ssrc), "r"(32768)
            : "memory");
        asm volatile("cp.async.bulk.commit_group;" ::: "memory");
        asm volatile("cp.async.bulk.wait_group 0;" ::: "memory");
    }
}

extern "C" void kernel_launch(void* const* d_in, const int* in_sizes, int n_in,
                              void* d_out, int out_size)
{
    const float* in      = (const float*)d_in[0];
    const int*   z_idx   = (const int*)d_in[1];
    const int*   row_idx = (const int*)d_in[2];
    const int*   col_idx = (const int*)d_in[3];
    float4* out = (float4*)d_out;

    const int n_vox = 64 * 64 * 64;         // 262144
    const int threads = 256;
    const int blocks = n_vox / threads;     // 1024
    sd3d_kernel<<<blocks, threads>>>(in, z_idx, row_idx, col_idx, out);
}

// round 9
// speedup vs baseline: 1.1895x; 1.1895x over previous
#include <cuda_runtime.h>
#include <cstdint>

// out[0, z, r, c, ch] = in[0, z_idx[z], row_idx[r], col_idx[c], 0]
// in (1,128,128,128,32) f32; idx arrays 64 x int32; out (1,64,64,64,32) f32.
//
// R3 schedule polished: 8 independent gather->store iterations per thread,
// 256-bit stores (st.global.v8.f32, STG.256): each lane writes 32B, a warp
// writes 1KB contiguous per instruction. 4 lanes share one gathered scalar.
// z/r idx loads are warp-uniform; 32-bit address arithmetic throughout.

#define N_V8     (8388608 / 8)      // 1,048,576 v8 stores total
#define STRIDE   (N_V8 / 8)         // 131,072 threads

__global__ __launch_bounds__(256) void sd3d_kernel(
    const float* __restrict__ in,
    const int*   __restrict__ z_idx,
    const int*   __restrict__ row_idx,
    const int*   __restrict__ col_idx,
    float*       __restrict__ out)
{
    unsigned t = blockIdx.x * blockDim.x + threadIdx.x;   // 0 .. 131,071

#pragma unroll
    for (int j = 0; j < 8; j++) {
        unsigned g = t + (unsigned)j * STRIDE;   // v8-store index, 0 .. 2^20-1
        unsigned v = g >> 2;                     // voxel id (4 lanes per voxel)
        unsigned c = v & 63;
        unsigned r = (v >> 6) & 63;
        unsigned z = v >> 12;

        unsigned zz = (unsigned)__ldg(z_idx + z);     // warp-uniform
        unsigned rr = (unsigned)__ldg(row_idx + r);   // warp-uniform
        unsigned cc = (unsigned)__ldg(col_idx + c);   // 8 distinct per warp

        float val = __ldg(in + (((zz << 7 | rr) << 7 | cc) << 5));

        float* p = out + (size_t)g * 8;   // 32B-aligned
        asm volatile(
            "st.global.v8.f32 [%0], {%1,%1,%1,%1,%1,%1,%1,%1};"
            :: "l"(p), "f"(val) : "memory");
    }
}

extern "C" void kernel_launch(void* const* d_in, const int* in_sizes, int n_in,
                              void* d_out, int out_size)
{
    const float* in      = (const float*)d_in[0];
    const int*   z_idx   = (const int*)d_in[1];
    const int*   row_idx = (const int*)d_in[2];
    const int*   col_idx = (const int*)d_in[3];
    float* out = (float*)d_out;

    const int threads = 256;
    const int blocks = STRIDE / threads;   // 512
    sd3d_kernel<<<blocks, threads>>>(in, z_idx, row_idx, col_idx, out);
}

// round 11
// speedup vs baseline: 1.2179x; 1.0239x over previous
#include <cuda_runtime.h>
#include <cstdint>

// out[0, z, r, c, ch] = in[0, z_idx[z], row_idx[r], col_idx[c], 0]
// in (1,128,128,128,32) f32; idx arrays 64 x int32; out (1,64,64,64,32) f32.
//
// 1M threads, one STG.256 (st.global.v8.f32) each: warp writes 1KB contiguous.
// 4 lanes share one gathered scalar. Gather uses ld.global.cs (each input
// sector is touched exactly once -> evict-first, keep L2 ways for the write
// stream). z/r idx loads warp-uniform, default-cached (heavily reused).

#define N_V8  (8388608 / 8)   // 1,048,576 v8 stores

__global__ __launch_bounds__(256) void sd3d_kernel(
    const float* __restrict__ in,
    const int*   __restrict__ z_idx,
    const int*   __restrict__ row_idx,
    const int*   __restrict__ col_idx,
    float*       __restrict__ out)
{
    unsigned g = blockIdx.x * blockDim.x + threadIdx.x;  // v8 index, 0..2^20-1
    unsigned v = g >> 2;                                 // voxel id (4 lanes/voxel)
    unsigned c = v & 63;
    unsigned r = (v >> 6) & 63;
    unsigned z = v >> 12;

    unsigned zz = (unsigned)__ldg(z_idx + z);     // warp-uniform
    unsigned rr = (unsigned)__ldg(row_idx + r);   // warp-uniform
    unsigned cc = (unsigned)__ldg(col_idx + c);   // 8 distinct per warp

    const float* src = in + (((zz << 7 | rr) << 7 | cc) << 5);
    float val;
    asm volatile("ld.global.cs.f32 %0, [%1];" : "=f"(val) : "l"(src));

    float* p = out + (size_t)g * 8;   // 32B-aligned
    asm volatile(
        "st.global.v8.f32 [%0], {%1,%1,%1,%1,%1,%1,%1,%1};"
        :: "l"(p), "f"(val) : "memory");
}

extern "C" void kernel_launch(void* const* d_in, const int* in_sizes, int n_in,
                              void* d_out, int out_size)
{
    const float* in      = (const float*)d_in[0];
    const int*   z_idx   = (const int*)d_in[1];
    const int*   row_idx = (const int*)d_in[2];
    const int*   col_idx = (const int*)d_in[3];
    float* out = (float*)d_out;

    const int threads = 256;
    const int blocks = N_V8 / threads;   // 4096
    sd3d_kernel<<<blocks, threads>>>(in, z_idx, row_idx, col_idx, out);
}